// round 16
// baseline (speedup 1.0000x reference)
#include <cuda_runtime.h>

typedef unsigned long long u64;
#define FULLMASK 0xffffffffu

// smem matrix stride in u64 units. 34: even stride -> 16B-aligned rows
// (LDS.128 legal) and A-row strided loads hit 8 distinct bank-pairs.
#define SS 34

// ---------------- scratch (static device globals; no runtime alloc) ---------
// element = float2 packed as u64 (batch 2p, batch 2p+1); matrices 32x32.
__device__ u64 g_chunk[28 * 64 * 1024];      // chunk products (28 sites each)
__device__ u64 g_l1[2 * 7 * 64 * 1024];      // level-1 tree products
__device__ u64 g_l2[2 * 3 * 64 * 1024];
__device__ u64 g_l3[2 * 2 * 64 * 1024];
__device__ u64 g_l4[2 * 64 * 1024];          // half products (left/right)

// ---------------- packed f32x2 helpers --------------------------------------
__device__ __forceinline__ u64 pack2(float x, float y) {
    u64 r; asm("mov.b64 %0,{%1,%2};" : "=l"(r) : "f"(x), "f"(y)); return r;
}
__device__ __forceinline__ void unpack2(u64 v, float &x, float &y) {
    asm("mov.b64 {%0,%1},%2;" : "=f"(x), "=f"(y) : "l"(v));
}
__device__ __forceinline__ void fma2(u64 &c, u64 a, u64 b) {
    asm("fma.rn.f32x2 %0,%1,%2,%0;" : "+l"(c) : "l"(a), "l"(b));
}

// ---------------- 2-warp 32x32 (f32x2) matmul --------------------------------
// C = A * B, A/B in smem row-major stride SS. Warp w owns rows 16w..16w+15.
// Lane (rg = lane>>2, cg = lane&3) tile: rows {rg+16w, rg+16w+8},
// cols {cg*8 .. cg*8+7}; c[cc] = row0, c[8+cc] = row1.
__device__ __forceinline__ void mm2(const u64 *A, const u64 *B, u64 c[16],
                                    int rg, int cg, int w) {
#pragma unroll
    for (int i = 0; i < 16; i++) c[i] = 0ull;
    int r0 = (rg + 16 * w) * SS, r1 = r0 + 8 * SS;
#pragma unroll 8
    for (int k = 0; k < 32; k++) {
        u64 a0 = A[r0 + k];
        u64 a1 = A[r1 + k];
        const ulonglong2 *bp = (const ulonglong2 *)&B[k * SS + cg * 8];
#pragma unroll
        for (int q = 0; q < 4; q++) {
            ulonglong2 b = bp[q];
            fma2(c[2 * q    ], a0, b.x);
            fma2(c[2 * q + 1], a0, b.y);
            fma2(c[2 * q + 8], a1, b.x);
            fma2(c[2 * q + 9], a1, b.y);
        }
    }
}

__device__ __forceinline__ void storeC2_smem(u64 *A, const u64 c[16],
                                             int rg, int cg, int w) {
    int r0 = (rg + 16 * w) * SS + cg * 8, r1 = r0 + 8 * SS;
#pragma unroll
    for (int cc = 0; cc < 8; cc += 2) {
        *(ulonglong2 *)&A[r0 + cc] = make_ulonglong2(c[cc], c[cc + 1]);
        *(ulonglong2 *)&A[r1 + cc] = make_ulonglong2(c[8 + cc], c[9 + cc]);
    }
}

__device__ __forceinline__ void storeC2_gmem(u64 *dst, const u64 c[16],
                                             int rg, int cg, int w) {
    int r0 = (rg + 16 * w) * 32 + cg * 8, r1 = r0 + 8 * 32;
#pragma unroll
    for (int cc = 0; cc < 8; cc += 2) {
        *(ulonglong2 *)&dst[r0 + cc] = make_ulonglong2(c[cc], c[cc + 1]);
        *(ulonglong2 *)&dst[r1 + cc] = make_ulonglong2(c[8 + cc], c[9 + cc]);
    }
}

// Build per-site matrix (M = c0 + x*(c1-c0), packed over batch pair) into smem.
// Warp w writes exactly rows 16w..16w+15 (its own mm2 A-rows).
__device__ __forceinline__ void buildM2(u64 *M, const float2 *__restrict__ coreSite,
                                        float x0, float x1, int lane, int w) {
#pragma unroll
    for (int t = 8 * w; t < 8 * w + 8; t++) {
        int e = t * 64 + lane * 2;                    // even element index i*32+j
        float4 cc = *(const float4 *)(coreSite + e);  // (c0,c1) of e and e+1
        float d0 = cc.y - cc.x;
        float d1 = cc.w - cc.z;
        u64 m0 = pack2(fmaf(x0, d0, cc.x), fmaf(x1, d0, cc.x));
        u64 m1 = pack2(fmaf(x0, d1, cc.z), fmaf(x1, d1, cc.z));
        int i = e >> 5, k = e & 31;
        *(ulonglong2 *)&M[i * SS + k] = make_ulonglong2(m0, m1);
    }
}

// Load a 32x32 u64 matrix from gmem (row-major, stride 32) into smem (stride SS).
__device__ __forceinline__ void load_mat(u64 *dst, const u64 *__restrict__ src,
                                         int tid) {
#pragma unroll
    for (int i = tid; i < 512; i += 64) {
        ulonglong2 v = *(const ulonglong2 *)(src + 2 * i);
        int g = 2 * i;
        *(ulonglong2 *)&dst[(g >> 5) * SS + (g & 31)] = v;
    }
}

// ---------------- kernel 1: chunk products ----------------------------------
// grid = 28 chunks * 64 pairs, 64 threads (2 warps). Chunk hc = sites
// [hc*28, hc*28+28); halves split at hc=14.
__global__ void __launch_bounds__(64, 12)
k_chunks(const float *__restrict__ xin, const float2 *__restrict__ core2) {
    __shared__ u64 Asm[32 * SS];
    __shared__ u64 Bsm[32 * SS];
    int tid = threadIdx.x;
    int w = tid >> 5, lane = tid & 31;
    int rg = lane >> 2, cg = lane & 3;
    int pair = blockIdx.x & 63;
    int hc   = blockIdx.x >> 6;           // 0..27
    int s0   = hc * 28;

    const float *xr0 = xin + (size_t)(2 * pair) * 784;
    const float *xr1 = xr0 + 784;

    buildM2(Asm, core2 + (size_t)s0 * 1024, __ldg(xr0 + s0), __ldg(xr1 + s0), lane, w);
    // no sync needed: warp w built exactly the A rows it will read

    u64 c[16];
    for (int step = 1; step < 28; step++) {
        int s = s0 + step;
        buildM2(Bsm, core2 + (size_t)s * 1024, __ldg(xr0 + s), __ldg(xr1 + s), lane, w);
        __syncthreads();                  // B fully built (all rows read by both warps)
        mm2(Asm, Bsm, c, rg, cg, w);
        __syncthreads();                  // both warps done reading B
        if (step < 27) storeC2_smem(Asm, c, rg, cg, w);   // own rows only
    }
    storeC2_gmem(g_chunk + ((size_t)hc * 64 + pair) * 1024, c, rg, cg, w);
}

// ---------------- tree levels -------------------------------------------------
__device__ __forceinline__ void level_body(const u64 *__restrict__ srcA,
                                           const u64 *__restrict__ srcB,
                                           u64 *__restrict__ dst) {
    __shared__ u64 Asm[32 * SS];
    __shared__ u64 Bsm[32 * SS];
    int tid = threadIdx.x;
    int w = tid >> 5, lane = tid & 31;
    int rg = lane >> 2, cg = lane & 3;
    load_mat(Asm, srcA, tid);
    load_mat(Bsm, srcB, tid);
    __syncthreads();
    u64 c[16];
    mm2(Asm, Bsm, c, rg, cg, w);
    storeC2_gmem(dst, c, rg, cg, w);
}

// L1: per half, 14 chunks -> 7.  grid = 2*7*64.
__global__ void __launch_bounds__(64) k_l1() {
    int pair = blockIdx.x & 63, q = blockIdx.x >> 6;   // q = half*7 + g
    int half = q / 7, g = q % 7;
    size_t m = (size_t)1024;
    level_body(g_chunk + (((size_t)half * 14 + 2 * g) * 64 + pair) * m,
               g_chunk + (((size_t)half * 14 + 2 * g + 1) * 64 + pair) * m,
               g_l1 + (((size_t)half * 7 + g) * 64 + pair) * m);
}
// L2: per half, p0..p5 -> 3 products (p6 carried).  grid = 2*3*64.
__global__ void __launch_bounds__(64) k_l2() {
    int pair = blockIdx.x & 63, q = blockIdx.x >> 6;
    int half = q / 3, g = q % 3;
    size_t m = (size_t)1024;
    level_body(g_l1 + (((size_t)half * 7 + 2 * g) * 64 + pair) * m,
               g_l1 + (((size_t)half * 7 + 2 * g + 1) * 64 + pair) * m,
               g_l2 + (((size_t)half * 3 + g) * 64 + pair) * m);
}
// L3: r0 = q0*q1 ; r1 = q2*p6.  grid = 2*2*64.
__global__ void __launch_bounds__(64) k_l3() {
    int pair = blockIdx.x & 63, q = blockIdx.x >> 6;
    int half = q / 2, o = q % 2;
    size_t m = (size_t)1024;
    const u64 *A, *B;
    if (o == 0) {
        A = g_l2 + (((size_t)half * 3 + 0) * 64 + pair) * m;
        B = g_l2 + (((size_t)half * 3 + 1) * 64 + pair) * m;
    } else {
        A = g_l2 + (((size_t)half * 3 + 2) * 64 + pair) * m;
        B = g_l1 + (((size_t)half * 7 + 6) * 64 + pair) * m;
    }
    level_body(A, B, g_l3 + (((size_t)half * 2 + o) * 64 + pair) * m);
}
// L4: half = r0*r1.  grid = 2*64.
__global__ void __launch_bounds__(64) k_l4() {
    int pair = blockIdx.x & 63, half = blockIdx.x >> 6;
    size_t m = (size_t)1024;
    level_body(g_l3 + (((size_t)half * 2 + 0) * 64 + pair) * m,
               g_l3 + (((size_t)half * 2 + 1) * 64 + pair) * m,
               g_l4 + ((size_t)half * 64 + pair) * m);
}

// ---------------- kernel: scores ---------------------------------------------
// scores[b,l] = sum_{jk} G[k,j] * label[j,k,l],  G = right * left.
// grid = 64 pairs, 64 threads (2 warps share the G matmul).
__global__ void __launch_bounds__(64)
k_scores(const float *__restrict__ label, float *__restrict__ out) {
    __shared__ u64 Asm[32 * SS];
    __shared__ u64 Bsm[32 * SS];
    __shared__ u64 part[2][10];
    int tid = threadIdx.x;
    int w = tid >> 5, lane = tid & 31;
    int rg = lane >> 2, cg = lane & 3;
    int pair = blockIdx.x;
    size_t m = (size_t)1024;

    load_mat(Asm, g_l4 + ((size_t)1 * 64 + pair) * m, tid);   // right -> A
    load_mat(Bsm, g_l4 + ((size_t)0 * 64 + pair) * m, tid);   // left  -> B
    __syncthreads();

    u64 c[16];
    mm2(Asm, Bsm, c, rg, cg, w);     // G rows k = rg+16w, rg+16w+8 ; cols j

    int k0 = rg + 16 * w, k1 = k0 + 8;
#pragma unroll
    for (int l = 0; l < 10; l++) {
        u64 acc = 0ull;
#pragma unroll
        for (int cc = 0; cc < 8; cc++) {
            int j = cg * 8 + cc;
            float v0 = __ldg(&label[(size_t)j * 320 + k0 * 10 + l]);
            float v1 = __ldg(&label[(size_t)j * 320 + k1 * 10 + l]);
            fma2(acc, c[cc    ], pack2(v0, v0));
            fma2(acc, c[8 + cc], pack2(v1, v1));
        }
#pragma unroll
        for (int off = 16; off; off >>= 1)
            acc = (u64)acc + 0;   // keep type; reduce below
        // warp reduce (u64 shuffle = packed pair of f32 sums)
        {
            float sx, sy; unpack2(acc, sx, sy);
#pragma unroll
            for (int off = 16; off; off >>= 1) {
                sx += __shfl_xor_sync(FULLMASK, sx, off);
                sy += __shfl_xor_sync(FULLMASK, sy, off);
            }
            if (lane == 0) part[w][l] = pack2(sx, sy);
        }
    }
    __syncthreads();
    if (tid < 10) {
        float ax, ay, bx_, by_;
        unpack2(part[0][tid], ax, ay);
        unpack2(part[1][tid], bx_, by_);
        out[(2 * pair    ) * 10 + tid] = ax + bx_;
        out[(2 * pair + 1) * 10 + tid] = ay + by_;
    }
}

// ---------------- launcher ---------------------------------------------------
extern "C" void kernel_launch(void *const *d_in, const int *in_sizes, int n_in,
                              void *d_out, int out_size) {
    const float  *xin   = (const float  *)d_in[0];   // (128, 784)
    const float2 *core2 = (const float2 *)d_in[1];   // (784, 32, 32, 2) over d
    const float  *label = (const float  *)d_in[2];   // (32, 32, 10)
    float *out = (float *)d_out;                     // (128, 10)

    k_chunks<<<28 * 64, 64>>>(xin, core2);
    k_l1    <<<2 * 7 * 64, 64>>>();
    k_l2    <<<2 * 3 * 64, 64>>>();
    k_l3    <<<2 * 2 * 64, 64>>>();
    k_l4    <<<2 * 64,     64>>>();
    k_scores<<<64,         64>>>(label, out);
}

// round 17
// speedup vs baseline: 1.6209x; 1.6209x over previous
#include <cuda_runtime.h>

typedef unsigned long long u64;
#define FULLMASK 0xffffffffu

// smem matrix row stride in u64 units. 34: even stride -> 16B-aligned rows
// (LDS.128 legal) and A-row strided loads hit 8 distinct bank-pairs.
#define SS 34

// ---------------- scratch (static device global; no runtime alloc) ----------
// g_chunk[hc][pair][32][32], hc = 0..27 (28-site chunks), element = packed f32x2.
__device__ u64 g_chunk[28 * 64 * 1024];   // 14.7 MB

// ---------------- packed f32x2 helpers --------------------------------------
__device__ __forceinline__ u64 pack2(float x, float y) {
    u64 r; asm("mov.b64 %0,{%1,%2};" : "=l"(r) : "f"(x), "f"(y)); return r;
}
__device__ __forceinline__ void unpack2(u64 v, float &x, float &y) {
    asm("mov.b64 {%0,%1},%2;" : "=f"(x), "=f"(y) : "l"(v));
}
__device__ __forceinline__ void fma2(u64 &c, u64 a, u64 b) {
    asm("fma.rn.f32x2 %0,%1,%2,%0;" : "+l"(c) : "l"(a), "l"(b));
}

// ---------------- 1-warp 32x32 (f32x2) matmul, strided operands -------------
// C = A * B. Lane (rg = lane>>2, cg = lane&3) owns rows {rg,rg+8,rg+16,rg+24},
// cols {cg*8..cg*8+7}. AS/BS are row strides in u64 units.
template <int AS, int BS>
__device__ __forceinline__ void mmT(const u64 *A, const u64 *B, u64 c[32],
                                    int rg, int cg) {
#pragma unroll
    for (int i = 0; i < 32; i++) c[i] = 0ull;
#pragma unroll 8
    for (int k = 0; k < 32; k++) {
        u64 a0 = A[(rg     ) * AS + k];
        u64 a1 = A[(rg +  8) * AS + k];
        u64 a2 = A[(rg + 16) * AS + k];
        u64 a3 = A[(rg + 24) * AS + k];
        const ulonglong2 *bp = (const ulonglong2 *)&B[k * BS + cg * 8];
        ulonglong2 b0 = bp[0], b1 = bp[1], b2 = bp[2], b3 = bp[3];
        u64 bb[8] = {b0.x, b0.y, b1.x, b1.y, b2.x, b2.y, b3.x, b3.y};
#pragma unroll
        for (int cc = 0; cc < 8; cc++) {
            fma2(c[cc     ], a0, bb[cc]);
            fma2(c[cc +  8], a1, bb[cc]);
            fma2(c[cc + 16], a2, bb[cc]);
            fma2(c[cc + 24], a3, bb[cc]);
        }
    }
}

template <int DS>
__device__ __forceinline__ void storeT(u64 *dst, const u64 c[32], int rg, int cg) {
#pragma unroll
    for (int t = 0; t < 4; t++)
#pragma unroll
        for (int cc = 0; cc < 8; cc += 2)
            *(ulonglong2 *)&dst[(rg + 8 * t) * DS + cg * 8 + cc] =
                make_ulonglong2(c[t * 8 + cc], c[t * 8 + cc + 1]);
}

// ---------------- site-matrix prefetch + build -------------------------------
// A site's core tensor slice is 1024 float2 (8KB). Per lane: 16 float4.
__device__ __forceinline__ void loadSite(float4 pf[16],
                                         const float2 *__restrict__ cs, int lane) {
#pragma unroll
    for (int t = 0; t < 16; t++)
        pf[t] = __ldg((const float4 *)(cs + t * 64 + lane * 2));
}

// M = c0 + x*(c1-c0), packed over the batch pair; write into smem stride SS.
__device__ __forceinline__ void buildFromRegs(u64 *M, const float4 pf[16],
                                              float x0, float x1, int lane) {
#pragma unroll
    for (int t = 0; t < 16; t++) {
        float4 cc = pf[t];
        float d0 = cc.y - cc.x;
        float d1 = cc.w - cc.z;
        u64 m0 = pack2(fmaf(x0, d0, cc.x), fmaf(x1, d0, cc.x));
        u64 m1 = pack2(fmaf(x0, d1, cc.z), fmaf(x1, d1, cc.z));
        int e = t * 64 + lane * 2;
        int i = e >> 5, k = e & 31;
        *(ulonglong2 *)&M[i * SS + k] = make_ulonglong2(m0, m1);
    }
}

// ---------------- kernel 1: chunk products ----------------------------------
// grid = 28 chunks * 64 pairs (one full wave at ~12 blocks/SM), 1 warp/block.
// Chunk hc covers sites [hc*28, hc*28+28). Next site's core data is
// register-prefetched so the LDG latency hides under the current matmul.
__global__ void __launch_bounds__(32, 12)
k_chunks(const float *__restrict__ xin, const float2 *__restrict__ core2) {
    __shared__ u64 Asm[32 * SS];
    __shared__ u64 Bsm[32 * SS];
    int lane = threadIdx.x;
    int rg = lane >> 2, cg = lane & 3;
    int pair = blockIdx.x & 63;
    int hc   = blockIdx.x >> 6;            // 0..27
    int s0   = hc * 28;

    const float *xr0 = xin + (size_t)(2 * pair) * 784;
    const float *xr1 = xr0 + 784;

    float4 pf[16];
    loadSite(pf, core2 + (size_t)s0 * 1024, lane);
    float xb0 = __ldg(xr0 + s0), xb1 = __ldg(xr1 + s0);
    buildFromRegs(Asm, pf, xb0, xb1, lane);

    // prefetch site s0+1
    loadSite(pf, core2 + (size_t)(s0 + 1) * 1024, lane);
    xb0 = __ldg(xr0 + s0 + 1); xb1 = __ldg(xr1 + s0 + 1);

    u64 c[32];
    for (int step = 1; step < 28; step++) {
        buildFromRegs(Bsm, pf, xb0, xb1, lane);       // consume prefetch
        if (step < 27) {                              // prefetch site step+1
            loadSite(pf, core2 + (size_t)(s0 + step + 1) * 1024, lane);
            xb0 = __ldg(xr0 + s0 + step + 1);
            xb1 = __ldg(xr1 + s0 + step + 1);
        }
        __syncwarp();            // B fully built (covers prior storeC -> mm too)
        mmT<SS, SS>(Asm, Bsm, c, rg, cg);
        __syncwarp();            // all lanes done reading A and B
        if (step < 27) storeT<SS>(Asm, c, rg, cg);
    }
    storeT<32>(g_chunk + ((size_t)hc * 64 + pair) * 1024, c, rg, cg);
}

// ---------------- kernel 2: fused tail (tree reduce + scores) ---------------
// grid = 64 (pair), 448 threads = 14 warps, dynamic smem:
//   slots[14] of 32*SS u64 (8704B each) + label[32*32*10] floats.
// L1: 14 warps, P_g^h = M_{2g} * M_{2g+1} read straight from gmem (L2-hot).
// L2..L4: in-place slot tree per half. G = right*left. scores via label smem.
#define SLOT(i) (sm + (size_t)(i) * (32 * SS))
#define TAIL_SMEM (14 * 32 * SS * 8 + 10240 * 4)

__global__ void __launch_bounds__(448)
k_tail(const float *__restrict__ label, float *__restrict__ out) {
    extern __shared__ u64 sm[];
    float *lbl = (float *)(sm + 14 * 32 * SS);
    int tid = threadIdx.x;
    int w = tid >> 5, lane = tid & 31;
    int rg = lane >> 2, cg = lane & 3;
    int pair = blockIdx.x;

    // stage label tensor (40KB) for the scores stage
    for (int i = tid; i < 10240; i += 448) lbl[i] = __ldg(label + i);

    // L1: warp w -> half h = w/7, leaf pair g = w%7 ; slots h*7+g
    {
        int h = w / 7, g = w % 7;
        const u64 *A = g_chunk + (((size_t)(h * 14 + 2 * g    )) * 64 + pair) * 1024;
        const u64 *B = g_chunk + (((size_t)(h * 14 + 2 * g + 1)) * 64 + pair) * 1024;
        u64 c[32];
        mmT<32, 32>(A, B, c, rg, cg);
        storeT<SS>(SLOT(h * 7 + g), c, rg, cg);
    }
    __syncthreads();

    // L2: 6 warps: slot(h,2g) <- slot(h,2g) * slot(h,2g+1), g=0..2, slot 6 carried
    if (w < 6) {
        int h = w / 3, g = w % 3;
        u64 c[32];
        mmT<SS, SS>(SLOT(h * 7 + 2 * g), SLOT(h * 7 + 2 * g + 1), c, rg, cg);
        storeT<SS>(SLOT(h * 7 + 2 * g), c, rg, cg);
    }
    __syncthreads();

    // L3: 4 warps: slot(h,0) <- slot(h,0)*slot(h,2); slot(h,4) <- slot(h,4)*slot(h,6)
    if (w < 4) {
        int h = w / 2, o = w % 2;
        u64 c[32];
        mmT<SS, SS>(SLOT(h * 7 + (o ? 4 : 0)), SLOT(h * 7 + (o ? 6 : 2)), c, rg, cg);
        storeT<SS>(SLOT(h * 7 + (o ? 4 : 0)), c, rg, cg);
    }
    __syncthreads();

    // L4: 2 warps: slot(h,0) <- slot(h,0) * slot(h,4)   (= half product)
    if (w < 2) {
        int h = w;
        u64 c[32];
        mmT<SS, SS>(SLOT(h * 7 + 0), SLOT(h * 7 + 4), c, rg, cg);
        storeT<SS>(SLOT(h * 7 + 0), c, rg, cg);
    }
    __syncthreads();

    // G = right * left  -> slot 1  (slot 7 = right, slot 0 = left)
    if (w == 0) {
        u64 c[32];
        mmT<SS, SS>(SLOT(7), SLOT(0), c, rg, cg);
        storeT<SS>(SLOT(1), c, rg, cg);
    }
    __syncthreads();

    // scores[b,l] = sum_{j,k} G[k,j] * label[j,k,l] ; warp w = label l, lane = j
    if (w < 10) {
        const u64 *G = SLOT(1);
        u64 acc = 0ull;
        int j = lane;
#pragma unroll
        for (int k = 0; k < 32; k++) {
            float v = lbl[j * 320 + k * 10 + w];
            fma2(acc, G[k * SS + j], pack2(v, v));
        }
        float sx, sy; unpack2(acc, sx, sy);
#pragma unroll
        for (int off = 16; off; off >>= 1) {
            sx += __shfl_xor_sync(FULLMASK, sx, off);
            sy += __shfl_xor_sync(FULLMASK, sy, off);
        }
        if (lane == 0) {
            out[(2 * pair    ) * 10 + w] = sx;
            out[(2 * pair + 1) * 10 + w] = sy;
        }
    }
}

// ---------------- launcher ---------------------------------------------------
extern "C" void kernel_launch(void *const *d_in, const int *in_sizes, int n_in,
                              void *d_out, int out_size) {
    const float  *xin   = (const float  *)d_in[0];   // (128, 784)
    const float2 *core2 = (const float2 *)d_in[1];   // (784, 32, 32, 2) over d
    const float  *label = (const float  *)d_in[2];   // (32, 32, 10)
    float *out = (float *)d_out;                     // (128, 10)

    cudaFuncSetAttribute(k_tail, cudaFuncAttributeMaxDynamicSharedMemorySize,
                         TAIL_SMEM);

    k_chunks<<<28 * 64, 32>>>(xin, core2);
    k_tail  <<<64, 448, TAIL_SMEM>>>(label, out);
}